// round 3
// baseline (speedup 1.0000x reference)
#include <cuda_runtime.h>
#include <cuda_bf16.h>
#include <cstdint>
#include <math.h>

#define B_ 8
#define T_ 4096
#define D_ 1024
#define H_ 64
#define BT_ (B_*T_)   // 32768

// tcgen05 only exists in the sm_103a/sm_100a feature set; the harness also runs a
// plain compute_103 PTX pass which must not see those instructions.
#if defined(__CUDA_ARCH_FEAT_SM103_ALL) || defined(__CUDA_ARCH_FEAT_SM100_ALL)
#define HAS_TC 1
#else
#define HAS_TC 0
#endif

// ---------------- scratch (device globals; allocation-free contract) ----------------
__device__ __nv_bfloat16 g_xn [(size_t)BT_*D_];      // normalized x, bf16
__device__ __nv_bfloat16 g_xbz[(size_t)BT_*2048];    // [x_b | z], bf16
__device__ __nv_bfloat16 g_xc [(size_t)BT_*D_];      // conv+silu output, bf16
__device__ float         g_proj[(size_t)BT_*1152];   // xc @ [dw;Bw;Dw]^T, fp32
__device__ float         g_a  [(size_t)512*4096];    // delta*A_log, [bh][t]
__device__ float         g_bu [(size_t)512*4096];    // delta*(p2+Bb), [bh][t]
__device__ __nv_bfloat16 g_h  [(size_t)BT_*H_];      // scan state, token-major
__device__ __nv_bfloat16 g_u  [(size_t)BT_*D_];      // gated pre-output, bf16
__device__ __nv_bfloat16 g_Wa [(size_t)2048*1024];   // [W1;W2]
__device__ __nv_bfloat16 g_Wb [(size_t)1152*1024];   // [dw;Bw;Dw]
__device__ __nv_bfloat16 g_Wc [(size_t)1024*64];     // Cw
__device__ __nv_bfloat16 g_Wd [(size_t)1024*1024];   // Wlast

// ---------------- helpers ----------------
__device__ __forceinline__ float siluf(float v){ return v / (1.f + expf(-v)); }
__device__ __forceinline__ float softplusf(float v){ return (v > 20.f) ? v : log1pf(expf(v)); }
__device__ __forceinline__ float clipf(float v){ return fminf(fmaxf(v, -20.f), 20.f); }

__device__ __forceinline__ void cpa16(uint32_t d, const void* s){
    asm volatile("cp.async.cg.shared.global [%0], [%1], 16;\n" :: "r"(d), "l"(s));
}
__device__ __forceinline__ void cpa_commit(){
    asm volatile("cp.async.commit_group;\n" ::: "memory");
}
__device__ __forceinline__ void cpa_wait_n(int n){
    if (n <= 0)      asm volatile("cp.async.wait_group 0;\n" ::: "memory");
    else if (n == 1) asm volatile("cp.async.wait_group 1;\n" ::: "memory");
    else             asm volatile("cp.async.wait_group 2;\n" ::: "memory");
}
__device__ __forceinline__ void mbar_wait(uint32_t addr, uint32_t parity){
    asm volatile(
        "{\n\t.reg .pred P;\n"
        "W_%=:\n\t"
        "mbarrier.try_wait.parity.shared.b64 P, [%0], %1;\n\t"
        "@P bra D_%=;\n\t"
        "bra W_%=;\n"
        "D_%=:\n\t}"
        :: "r"(addr), "r"(parity) : "memory");
}
// SW128 K-major smem descriptor (layout=2, version=1, SBO=64, LBO=1)
__device__ __forceinline__ uint64_t sdesc(uint32_t a){
    return ((uint64_t)2 << 61) | ((uint64_t)1 << 46) | ((uint64_t)64 << 32)
         | ((uint64_t)1 << 16) | ((a >> 4) & 0x3FFF);
}
__device__ __forceinline__ void mma_f16_ss(uint32_t dt, uint64_t ad, uint64_t bd,
                                           uint32_t idesc, uint32_t en){
#if HAS_TC
    asm volatile(
        "{\n\t.reg .pred p;\n\t"
        "setp.ne.u32 p, %5, 0;\n\t"
        "tcgen05.mma.cta_group::1.kind::f16 [%0], %1, %2, %3, {%4,%4,%4,%4}, p;\n\t}"
        :: "r"(dt), "l"(ad), "l"(bd), "r"(idesc), "r"(0u), "r"(en) : "memory");
#endif
}
__device__ __forceinline__ void ldtm32(uint32_t addr, uint32_t* r){
#if HAS_TC
    asm volatile(
        "tcgen05.ld.sync.aligned.32x32b.x32.b32 "
        "{%0,%1,%2,%3,%4,%5,%6,%7,%8,%9,%10,%11,%12,%13,%14,%15,"
        "%16,%17,%18,%19,%20,%21,%22,%23,%24,%25,%26,%27,%28,%29,%30,%31}, [%32];"
        : "=r"(r[0]),"=r"(r[1]),"=r"(r[2]),"=r"(r[3]),"=r"(r[4]),"=r"(r[5]),"=r"(r[6]),"=r"(r[7]),
          "=r"(r[8]),"=r"(r[9]),"=r"(r[10]),"=r"(r[11]),"=r"(r[12]),"=r"(r[13]),"=r"(r[14]),"=r"(r[15]),
          "=r"(r[16]),"=r"(r[17]),"=r"(r[18]),"=r"(r[19]),"=r"(r[20]),"=r"(r[21]),"=r"(r[22]),"=r"(r[23]),
          "=r"(r[24]),"=r"(r[25]),"=r"(r[26]),"=r"(r[27]),"=r"(r[28]),"=r"(r[29]),"=r"(r[30]),"=r"(r[31])
        : "r"(addr));
#else
    #pragma unroll
    for (int i = 0; i < 32; i++) r[i] = 0u;
    (void)addr;
#endif
}
__device__ __forceinline__ void tc_alloc(uint32_t smem_addr, uint32_t ncols){
#if HAS_TC
    asm volatile("tcgen05.alloc.cta_group::1.sync.aligned.shared::cta.b32 [%0], %1;"
                 :: "r"(smem_addr), "r"(ncols) : "memory");
#endif
}
__device__ __forceinline__ void tc_dealloc(uint32_t tmem, uint32_t ncols){
#if HAS_TC
    asm volatile("tcgen05.relinquish_alloc_permit.cta_group::1.sync.aligned;");
    asm volatile("tcgen05.dealloc.cta_group::1.sync.aligned.b32 %0, %1;" :: "r"(tmem), "r"(ncols));
#endif
}
__device__ __forceinline__ void tc_commit(uint32_t mbar){
#if HAS_TC
    asm volatile("tcgen05.commit.cta_group::1.mbarrier::arrive::one.shared::cluster.b64 [%0];"
                 :: "r"(mbar) : "memory");
#endif
}
__device__ __forceinline__ void tc_fence_after(){
#if HAS_TC
    asm volatile("tcgen05.fence::after_thread_sync;" ::: "memory");
#endif
}
__device__ __forceinline__ void tc_wait_ld(){
#if HAS_TC
    asm volatile("tcgen05.wait::ld.sync.aligned;" ::: "memory");
#endif
}

// ---------------- weight conversion / packing ----------------
__global__ void convert_weights(const float* __restrict__ W1, const float* __restrict__ W2,
                                const float* __restrict__ dwp, const float* __restrict__ Bwp,
                                const float* __restrict__ Dwp, const float* __restrict__ Cwp,
                                const float* __restrict__ Wlastp){
    int i = blockIdx.x * blockDim.x + threadIdx.x;
    const int NWa = 2048*1024, NWb = 1152*1024, NWc = 1024*64, NWd = 1024*1024;
    if (i < NWa){
        g_Wa[i] = __float2bfloat16(i < 1048576 ? W1[i] : W2[i - 1048576]);
    } else if (i < NWa + NWb){
        int j = i - NWa;
        float v = (j < 65536) ? dwp[j] : (j < 131072) ? Bwp[j - 65536] : Dwp[j - 131072];
        g_Wb[j] = __float2bfloat16(v);
    } else if (i < NWa + NWb + NWc){
        int j = i - NWa - NWb;
        g_Wc[j] = __float2bfloat16(Cwp[j]);
    } else if (i < NWa + NWb + NWc + NWd){
        int j = i - NWa - NWb - NWc;
        g_Wd[j] = __float2bfloat16(Wlastp[j]);
    }
}

// ---------------- RMSNorm ----------------
__global__ void rmsnorm_kernel(const float* __restrict__ x, const float* __restrict__ w){
    __shared__ float ws[8];
    int m = blockIdx.x, tid = threadIdx.x;
    float4 v = ((const float4*)(x + (size_t)m * D_))[tid];
    float ss = v.x*v.x + v.y*v.y + v.z*v.z + v.w*v.w;
    #pragma unroll
    for (int d = 16; d; d >>= 1) ss += __shfl_xor_sync(0xffffffffu, ss, d);
    if ((tid & 31) == 0) ws[tid >> 5] = ss;
    __syncthreads();
    if (tid == 0){ float s = 0.f; for (int i = 0; i < 8; i++) s += ws[i]; ws[0] = s; }
    __syncthreads();
    float scale = rsqrtf(ws[0] * (1.f / D_) + 1.1920928955078125e-07f);
    float4 wv = ((const float4*)w)[tid];
    __nv_bfloat162 p0 = __floats2bfloat162_rn(v.x*scale*wv.x, v.y*scale*wv.y);
    __nv_bfloat162 p1 = __floats2bfloat162_rn(v.z*scale*wv.z, v.w*scale*wv.w);
    __nv_bfloat162* dst = (__nv_bfloat162*)(g_xn + (size_t)m * D_) + tid * 2;
    dst[0] = p0; dst[1] = p1;
}

// ---------------- causal depthwise conv (k=3) + SiLU ----------------
__global__ void conv_silu_kernel(const float* __restrict__ conv_w, const float* __restrict__ conv_b){
    int idx = blockIdx.x * blockDim.x + threadIdx.x;
    int d2 = idx & 511; int bt = idx >> 9;
    int t = bt & (T_ - 1);
    int d = d2 * 2;
    const __nv_bfloat162* row2 = (const __nv_bfloat162*)(g_xbz + (size_t)bt * 2048 + d);
    __nv_bfloat162 zero2; zero2.x = __float2bfloat16(0.f); zero2.y = __float2bfloat16(0.f);
    __nv_bfloat162 c2 = *row2;
    __nv_bfloat162 c1 = (t >= 1) ? *(const __nv_bfloat162*)(g_xbz + (size_t)(bt-1) * 2048 + d) : zero2;
    __nv_bfloat162 c0 = (t >= 2) ? *(const __nv_bfloat162*)(g_xbz + (size_t)(bt-2) * 2048 + d) : zero2;
    float w00 = conv_w[d*3+0], w01 = conv_w[d*3+1], w02 = conv_w[d*3+2];
    float w10 = conv_w[d*3+3], w11 = conv_w[d*3+4], w12 = conv_w[d*3+5];
    float r0 = __bfloat162float(c0.x)*w00 + __bfloat162float(c1.x)*w01 + __bfloat162float(c2.x)*w02 + conv_b[d];
    float r1 = __bfloat162float(c0.y)*w10 + __bfloat162float(c1.y)*w11 + __bfloat162float(c2.y)*w12 + conv_b[d+1];
    r0 = siluf(r0); r1 = siluf(r1);
    *(__nv_bfloat162*)(g_xc + (size_t)bt * 1024 + d) = __floats2bfloat162_rn(r0, r1);
}

// ---------------- scan prep ----------------
__global__ void prep_scan_kernel(const float* __restrict__ Aparam, const float* __restrict__ Bb,
                                 const float* __restrict__ db){
    __shared__ float sm[64][129];
    int row0 = blockIdx.x * 64;
    int tid = threadIdx.x;
    for (int idx = tid; idx < 64*128; idx += 256){
        int r = idx >> 7, c = idx & 127;
        sm[r][c] = g_proj[(size_t)(row0 + r) * 1152 + c];
    }
    __syncthreads();
    int b = row0 >> 12;
    int t0 = row0 & (T_ - 1);
    for (int idx = tid; idx < 64*64; idx += 256){
        int h = idx >> 6, tt = idx & 63;
        float p1 = sm[tt][h], p2 = sm[tt][64 + h];
        float delta = softplusf(p1 + db[h]);
        float alog = -softplusf(Aparam[h]);
        size_t o = (size_t)(b * 64 + h) * 4096 + t0 + tt;
        g_a[o]  = delta * alog;
        g_bu[o] = delta * (p2 + Bb[h]);
    }
}

// ---------------- block-parallel scan over T per (b,h) ----------------
__device__ __forceinline__ float block_excl_prefix(float total, float* wsum, int tid){
    __syncthreads();
    int lane = tid & 31, wid = tid >> 5;
    float v = total;
    #pragma unroll
    for (int d = 1; d < 32; d <<= 1){
        float o = __shfl_up_sync(0xffffffffu, v, d);
        if (lane >= d) v += o;
    }
    if (lane == 31) wsum[wid] = v;
    __syncthreads();
    if (tid == 0){
        float s = 0.f;
        for (int i = 0; i < 16; i++){ float t = wsum[i]; wsum[i] = s; s += t; }
    }
    __syncthreads();
    return wsum[wid] + v - total;
}

__global__ void scan_kernel(){
    __shared__ float wsum[16];
    int bh = blockIdx.x;
    int b = bh >> 6, hh = bh & 63;
    int tid = threadIdx.x;
    size_t base = (size_t)bh * 4096 + tid * 8;
    float av[8], bv[8], ev[8], cv[8];
    {
        float4 a0 = *(const float4*)(g_a + base);
        float4 a1 = *(const float4*)(g_a + base + 4);
        av[0]=a0.x; av[1]=a0.y; av[2]=a0.z; av[3]=a0.w;
        av[4]=a1.x; av[5]=a1.y; av[6]=a1.z; av[7]=a1.w;
        float4 b0 = *(const float4*)(g_bu + base);
        float4 b1 = *(const float4*)(g_bu + base + 4);
        bv[0]=b0.x; bv[1]=b0.y; bv[2]=b0.z; bv[3]=b0.w;
        bv[4]=b1.x; bv[5]=b1.y; bv[6]=b1.z; bv[7]=b1.w;
    }
    float s = 0.f;
    #pragma unroll
    for (int i = 0; i < 8; i++){ s += av[i]; av[i] = s; }
    float pa = block_excl_prefix(av[7], wsum, tid);
    #pragma unroll
    for (int i = 0; i < 8; i++){
        float S = pa + av[i];
        float Sprev = pa + (i ? av[i-1] : 0.f);
        ev[i] = expf(clipf(S));
        cv[i] = bv[i] * expf(-clipf(Sprev));
    }
    s = 0.f;
    #pragma unroll
    for (int i = 0; i < 8; i++){ s += cv[i]; cv[i] = s; }
    float pb = block_excl_prefix(cv[7], wsum, tid);
    int t = tid * 8;
    #pragma unroll
    for (int i = 0; i < 8; i++){
        float hval = ev[i] * (pb + cv[i]);
        g_h[(size_t)(b * T_ + t + i) * 64 + hh] = __float2bfloat16(hval);
    }
}

// ---------------- tcgen05 GEMM: C[M,N] = A[M,K] @ W[N,K]^T, fused epilogues ----------------
// EPI 0: store bf16 to g_xbz (ld 2048)
// EPI 1: store f32  to g_proj (ld 1152)
// EPI 2: u = (acc + Cb + Db + projDw) * silu(z) -> g_u bf16
// EPI 3: out = acc + x (fp32)
template<int EPI, int KDIM, int NTILE>
__global__ void __launch_bounds__(128, 1) gemm_tc(
    const float* __restrict__ aux0, const float* __restrict__ aux1,
    const float* __restrict__ xres, float* __restrict__ outp)
{
    const __nv_bfloat16* __restrict__ Ag = (EPI==0) ? g_xn : (EPI==1) ? g_xc : (EPI==2) ? g_h : g_u;
    const __nv_bfloat16* __restrict__ Wg = (EPI==0) ? g_Wa : (EPI==1) ? g_Wb : (EPI==2) ? g_Wc : g_Wd;
    extern __shared__ __align__(1024) char smem_raw[];
    constexpr int S = 4;
    constexpr int KT = KDIM / 64;
    constexpr int STAGE = 16384 + NTILE * 128;     // A tile 16KB + W tile
    constexpr uint32_t IDESC = (1u<<4) | (1u<<7) | (1u<<10) | ((NTILE/8u)<<17) | (8u<<24);

    const int tid = threadIdx.x, lane = tid & 31, warp = tid >> 5;
    const size_t m0 = (size_t)blockIdx.y * 128;
    const int n0 = blockIdx.x * NTILE;
    const uint32_t sbase = (uint32_t)__cvta_generic_to_shared(smem_raw);
    const uint32_t mb = sbase + 16;

    if (warp == 0) tc_alloc(sbase, 256u);
    if (tid == 0){
        #pragma unroll
        for (int s = 0; s < S; s++)
            asm volatile("mbarrier.init.shared.b64 [%0], 1;" :: "r"(mb + 8*s) : "memory");
    }
    __syncthreads();
    uint32_t tmem;
    asm volatile("ld.shared.b32 %0, [%1];" : "=r"(tmem) : "r"(sbase));

    auto load_chunk = [&](int k, int st){
        uint32_t abase = sbase + 1024 + st * STAGE;
        uint32_t wbase = abase + 16384;
        const __nv_bfloat16* As = Ag + m0 * KDIM + k * 64;
        const __nv_bfloat16* Ws = Wg + (size_t)n0 * KDIM + k * 64;
        #pragma unroll
        for (int i = 0; i < 8; i++){
            int idx = i * 128 + tid;
            int r = idx >> 3, c = idx & 7;
            cpa16(abase + r*128 + ((c ^ (r & 7)) << 4), As + (size_t)r * KDIM + c * 8);
        }
        #pragma unroll
        for (int i = 0; i < NTILE/16; i++){
            int idx = i * 128 + tid;
            int r = idx >> 3, c = idx & 7;
            cpa16(wbase + r*128 + ((c ^ (r & 7)) << 4), Ws + (size_t)r * KDIM + c * 8);
        }
        cpa_commit();
    };

    // prologue: stages 0..S-2
    constexpr int PRO = (S-1 < KT) ? S-1 : KT;
    for (int k = 0; k < PRO; k++) load_chunk(k, k);

    for (int k = 0; k < KT; k++){
        const int st = k & (S-1);
        int rem = KT - 1 - k;
        cpa_wait_n(rem < S-2 ? rem : S-2);
        __syncthreads();
        if (tid == 0){
            asm volatile("fence.proxy.async.shared::cta;" ::: "memory");
            uint32_t ab = sbase + 1024 + st * STAGE;
            uint64_t ad = sdesc(ab), bd = sdesc(ab + 16384);
            #pragma unroll
            for (int ks = 0; ks < 4; ks++)
                mma_f16_ss(tmem, ad + ks*2, bd + ks*2, IDESC, (k == 0 && ks == 0) ? 0u : 1u);
            tc_commit(mb + 8*st);
        }
        if (k + S - 1 < KT){
            if (k >= 1) mbar_wait(mb + 8*((k-1) & (S-1)), ((k-1) / S) & 1);
            load_chunk(k + S - 1, (k + S - 1) & (S-1));
        }
    }
    // wait final MMA
    mbar_wait(mb + 8*((KT-1) & (S-1)), ((KT-1) / S) & 1);
    tc_fence_after();
    __syncthreads();

    // TMEM -> padded SMEM (row-major, stride NTILE+1 floats)
    float* sp = (float*)(smem_raw + 1024);
    {
        const int row = warp * 32 + lane;
        #pragma unroll
        for (int g = 0; g < NTILE/32; g++){
            uint32_t r32[32];
            ldtm32(tmem + g*32, r32);
            tc_wait_ld();
            uint32_t baddr = sbase + 1024 + (uint32_t)(row*(NTILE+1) + g*32) * 4;
            #pragma unroll
            for (int c = 0; c < 32; c++)
                asm volatile("st.shared.b32 [%0], %1;" :: "r"(baddr + c*4), "r"(r32[c]));
        }
    }
    __syncthreads();
    if (warp == 0) tc_dealloc(tmem, 256u);

    // coalesced global epilogue
    #pragma unroll 4
    for (int it = 0; it < NTILE/2; it++){
        int i = it * 128 + tid;
        int r = i / (NTILE/2), c2 = i % (NTILE/2);
        float v0 = sp[r*(NTILE+1) + c2*2];
        float v1 = sp[r*(NTILE+1) + c2*2 + 1];
        int m = (int)m0 + r;
        int nb = n0 + c2*2;
        if (EPI == 0){
            *(__nv_bfloat162*)(g_xbz + (size_t)m * 2048 + nb) = __floats2bfloat162_rn(v0, v1);
        } else if (EPI == 1){
            *(float2*)(g_proj + (size_t)m * 1152 + nb) = make_float2(v0, v1);
        } else if (EPI == 2){
            __nv_bfloat162 zz = *(const __nv_bfloat162*)(g_xbz + (size_t)m * 2048 + 1024 + nb);
            float z0 = __bfloat162float(zz.x), z1 = __bfloat162float(zz.y);
            float2 dd = *(const float2*)(g_proj + (size_t)m * 1152 + 128 + nb);
            float u0 = (v0 + aux0[nb]   + aux1[nb]   + dd.x) * siluf(z0);
            float u1 = (v1 + aux0[nb+1] + aux1[nb+1] + dd.y) * siluf(z1);
            *(__nv_bfloat162*)(g_u + (size_t)m * 1024 + nb) = __floats2bfloat162_rn(u0, u1);
        } else {
            float2 xr = *(const float2*)(xres + (size_t)m * 1024 + nb);
            *(float2*)(outp + (size_t)m * 1024 + nb) = make_float2(v0 + xr.x, v1 + xr.y);
        }
    }
}

// ---------------- launch ----------------
extern "C" void kernel_launch(void* const* d_in, const int* in_sizes, int n_in,
                              void* d_out, int out_size){
    const float* x      = (const float*)d_in[0];
    const float* norm_w = (const float*)d_in[1];
    const float* W1     = (const float*)d_in[2];
    const float* W2     = (const float*)d_in[3];
    const float* Wlast  = (const float*)d_in[4];
    const float* conv_w = (const float*)d_in[5];
    const float* conv_b = (const float*)d_in[6];
    const float* Ap     = (const float*)d_in[7];
    const float* Bw     = (const float*)d_in[8];
    const float* Bb     = (const float*)d_in[9];
    const float* Cw     = (const float*)d_in[10];
    const float* Cb     = (const float*)d_in[11];
    const float* Dw     = (const float*)d_in[12];
    const float* Db     = (const float*)d_in[13];
    const float* dwp    = (const float*)d_in[14];
    const float* dbp    = (const float*)d_in[15];
    float* out = (float*)d_out;

    const int SM256 = 1024 + 4*(16384 + 256*128);   // 197632
    const int SM128 = 1024 + 4*(16384 + 128*128);   // 132096
    cudaFuncSetAttribute((const void*)gemm_tc<0,1024,256>, cudaFuncAttributeMaxDynamicSharedMemorySize, SM256);
    cudaFuncSetAttribute((const void*)gemm_tc<1,1024,128>, cudaFuncAttributeMaxDynamicSharedMemorySize, SM128);
    cudaFuncSetAttribute((const void*)gemm_tc<2,64,256>,   cudaFuncAttributeMaxDynamicSharedMemorySize, SM256);
    cudaFuncSetAttribute((const void*)gemm_tc<3,1024,256>, cudaFuncAttributeMaxDynamicSharedMemorySize, SM256);

    convert_weights<<<17152, 256>>>(W1, W2, dwp, Bw, Dw, Cw, Wlast);
    rmsnorm_kernel<<<32768, 256>>>(x, norm_w);
    gemm_tc<0,1024,256><<<dim3(8, 256), 128, SM256>>>(nullptr, nullptr, nullptr, nullptr);
    conv_silu_kernel<<<65536, 256>>>(conv_w, conv_b);
    gemm_tc<1,1024,128><<<dim3(9, 256), 128, SM128>>>(nullptr, nullptr, nullptr, nullptr);
    prep_scan_kernel<<<512, 256>>>(Ap, Bb, dbp);
    scan_kernel<<<512, 512>>>();
    gemm_tc<2,64,256><<<dim3(4, 256), 128, SM256>>>(Cb, Db, nullptr, nullptr);
    gemm_tc<3,1024,256><<<dim3(4, 256), 128, SM256>>>(nullptr, nullptr, x, out);
}

// round 4
// speedup vs baseline: 1.4026x; 1.4026x over previous
#include <cuda_runtime.h>
#include <cuda_bf16.h>
#include <cstdint>
#include <math.h>

#define B_ 8
#define T_ 4096
#define D_ 1024
#define H_ 64
#define BT_ (B_*T_)   // 32768

// tcgen05 only exists in the sm_103a/sm_100a feature set; the harness also runs a
// plain compute_103 PTX pass which must not see those instructions.
#if defined(__CUDA_ARCH_FEAT_SM103_ALL) || defined(__CUDA_ARCH_FEAT_SM100_ALL)
#define HAS_TC 1
#else
#define HAS_TC 0
#endif

// ---------------- scratch (device globals; allocation-free contract) ----------------
__device__ __nv_bfloat16 g_xn [(size_t)BT_*D_];      // normalized x, bf16
__device__ __nv_bfloat16 g_xbz[(size_t)BT_*2048];    // [x_b | z], bf16
__device__ __nv_bfloat16 g_xc [(size_t)BT_*D_];      // conv+silu output, bf16
__device__ float         g_proj[(size_t)BT_*1152];   // xc @ [dw;Bw;Dw]^T, fp32
__device__ float         g_a  [(size_t)512*4096];    // delta*A_log, [bh][t]
__device__ float         g_bu [(size_t)512*4096];    // delta*(p2+Bb), [bh][t]
__device__ __nv_bfloat16 g_h  [(size_t)BT_*H_];      // scan state, token-major
__device__ __nv_bfloat16 g_u  [(size_t)BT_*D_];      // gated pre-output, bf16
__device__ __nv_bfloat16 g_Wa [(size_t)2048*1024];   // [W1;W2]
__device__ __nv_bfloat16 g_Wb [(size_t)1152*1024];   // [dw;Bw;Dw]
__device__ __nv_bfloat16 g_Wc [(size_t)1024*64];     // Cw
__device__ __nv_bfloat16 g_Wd [(size_t)1024*1024];   // Wlast

// ---------------- helpers ----------------
__device__ __forceinline__ float siluf(float v){ return v / (1.f + expf(-v)); }
__device__ __forceinline__ float softplusf(float v){ return (v > 20.f) ? v : log1pf(expf(v)); }
__device__ __forceinline__ float clipf(float v){ return fminf(fmaxf(v, -20.f), 20.f); }

__device__ __forceinline__ void cpa16(uint32_t d, const void* s){
    asm volatile("cp.async.cg.shared.global [%0], [%1], 16;\n" :: "r"(d), "l"(s));
}
__device__ __forceinline__ void cpa_commit(){
    asm volatile("cp.async.commit_group;\n" ::: "memory");
}
__device__ __forceinline__ void cpa_wait0(){
    asm volatile("cp.async.wait_group 0;\n" ::: "memory");
}
__device__ __forceinline__ void mbar_wait(uint32_t addr, uint32_t parity){
    asm volatile(
        "{\n\t.reg .pred P;\n"
        "W_%=:\n\t"
        "mbarrier.try_wait.parity.shared.b64 P, [%0], %1;\n\t"
        "@P bra D_%=;\n\t"
        "bra W_%=;\n"
        "D_%=:\n\t}"
        :: "r"(addr), "r"(parity) : "memory");
}
// SW128 K-major smem descriptor (layout=2, version=1, SBO=64, LBO=1)
__device__ __forceinline__ uint64_t sdesc(uint32_t a){
    return ((uint64_t)2 << 61) | ((uint64_t)1 << 46) | ((uint64_t)64 << 32)
         | ((uint64_t)1 << 16) | ((a >> 4) & 0x3FFF);
}
__device__ __forceinline__ void mma_f16_ss(uint32_t dt, uint64_t ad, uint64_t bd,
                                           uint32_t idesc, uint32_t en){
#if HAS_TC
    asm volatile(
        "{\n\t.reg .pred p;\n\t"
        "setp.ne.u32 p, %5, 0;\n\t"
        "tcgen05.mma.cta_group::1.kind::f16 [%0], %1, %2, %3, {%4,%4,%4,%4}, p;\n\t}"
        :: "r"(dt), "l"(ad), "l"(bd), "r"(idesc), "r"(0u), "r"(en) : "memory");
#endif
}
__device__ __forceinline__ void ldtm32(uint32_t addr, uint32_t* r){
#if HAS_TC
    asm volatile(
        "tcgen05.ld.sync.aligned.32x32b.x32.b32 "
        "{%0,%1,%2,%3,%4,%5,%6,%7,%8,%9,%10,%11,%12,%13,%14,%15,"
        "%16,%17,%18,%19,%20,%21,%22,%23,%24,%25,%26,%27,%28,%29,%30,%31}, [%32];"
        : "=r"(r[0]),"=r"(r[1]),"=r"(r[2]),"=r"(r[3]),"=r"(r[4]),"=r"(r[5]),"=r"(r[6]),"=r"(r[7]),
          "=r"(r[8]),"=r"(r[9]),"=r"(r[10]),"=r"(r[11]),"=r"(r[12]),"=r"(r[13]),"=r"(r[14]),"=r"(r[15]),
          "=r"(r[16]),"=r"(r[17]),"=r"(r[18]),"=r"(r[19]),"=r"(r[20]),"=r"(r[21]),"=r"(r[22]),"=r"(r[23]),
          "=r"(r[24]),"=r"(r[25]),"=r"(r[26]),"=r"(r[27]),"=r"(r[28]),"=r"(r[29]),"=r"(r[30]),"=r"(r[31])
        : "r"(addr));
#else
    #pragma unroll
    for (int i = 0; i < 32; i++) r[i] = 0u;
    (void)addr;
#endif
}
__device__ __forceinline__ void tc_alloc(uint32_t smem_addr, uint32_t ncols){
#if HAS_TC
    asm volatile("tcgen05.alloc.cta_group::1.sync.aligned.shared::cta.b32 [%0], %1;"
                 :: "r"(smem_addr), "r"(ncols) : "memory");
#endif
}
__device__ __forceinline__ void tc_dealloc(uint32_t tmem, uint32_t ncols){
#if HAS_TC
    asm volatile("tcgen05.relinquish_alloc_permit.cta_group::1.sync.aligned;");
    asm volatile("tcgen05.dealloc.cta_group::1.sync.aligned.b32 %0, %1;" :: "r"(tmem), "r"(ncols));
#endif
}
__device__ __forceinline__ void tc_commit(uint32_t mbar){
#if HAS_TC
    asm volatile("tcgen05.commit.cta_group::1.mbarrier::arrive::one.shared::cluster.b64 [%0];"
                 :: "r"(mbar) : "memory");
#endif
}
__device__ __forceinline__ void tc_fence_after(){
#if HAS_TC
    asm volatile("tcgen05.fence::after_thread_sync;" ::: "memory");
#endif
}
__device__ __forceinline__ void tc_wait_ld(){
#if HAS_TC
    asm volatile("tcgen05.wait::ld.sync.aligned;" ::: "memory");
#endif
}

// ---------------- weight conversion / packing ----------------
__global__ void convert_weights(const float* __restrict__ W1, const float* __restrict__ W2,
                                const float* __restrict__ dwp, const float* __restrict__ Bwp,
                                const float* __restrict__ Dwp, const float* __restrict__ Cwp,
                                const float* __restrict__ Wlastp){
    int i = blockIdx.x * blockDim.x + threadIdx.x;
    const int NWa = 2048*1024, NWb = 1152*1024, NWc = 1024*64, NWd = 1024*1024;
    if (i < NWa){
        g_Wa[i] = __float2bfloat16(i < 1048576 ? W1[i] : W2[i - 1048576]);
    } else if (i < NWa + NWb){
        int j = i - NWa;
        float v = (j < 65536) ? dwp[j] : (j < 131072) ? Bwp[j - 65536] : Dwp[j - 131072];
        g_Wb[j] = __float2bfloat16(v);
    } else if (i < NWa + NWb + NWc){
        int j = i - NWa - NWb;
        g_Wc[j] = __float2bfloat16(Cwp[j]);
    } else if (i < NWa + NWb + NWc + NWd){
        int j = i - NWa - NWb - NWc;
        g_Wd[j] = __float2bfloat16(Wlastp[j]);
    }
}

// ---------------- RMSNorm ----------------
__global__ void rmsnorm_kernel(const float* __restrict__ x, const float* __restrict__ w){
    __shared__ float ws[8];
    int m = blockIdx.x, tid = threadIdx.x;
    float4 v = ((const float4*)(x + (size_t)m * D_))[tid];
    float ss = v.x*v.x + v.y*v.y + v.z*v.z + v.w*v.w;
    #pragma unroll
    for (int d = 16; d; d >>= 1) ss += __shfl_xor_sync(0xffffffffu, ss, d);
    if ((tid & 31) == 0) ws[tid >> 5] = ss;
    __syncthreads();
    if (tid == 0){ float s = 0.f; for (int i = 0; i < 8; i++) s += ws[i]; ws[0] = s; }
    __syncthreads();
    float scale = rsqrtf(ws[0] * (1.f / D_) + 1.1920928955078125e-07f);
    float4 wv = ((const float4*)w)[tid];
    __nv_bfloat162 p0 = __floats2bfloat162_rn(v.x*scale*wv.x, v.y*scale*wv.y);
    __nv_bfloat162 p1 = __floats2bfloat162_rn(v.z*scale*wv.z, v.w*scale*wv.w);
    __nv_bfloat162* dst = (__nv_bfloat162*)(g_xn + (size_t)m * D_) + tid * 2;
    dst[0] = p0; dst[1] = p1;
}

// ---------------- causal depthwise conv (k=3) + SiLU ----------------
__global__ void conv_silu_kernel(const float* __restrict__ conv_w, const float* __restrict__ conv_b){
    int idx = blockIdx.x * blockDim.x + threadIdx.x;
    int d2 = idx & 511; int bt = idx >> 9;
    int t = bt & (T_ - 1);
    int d = d2 * 2;
    const __nv_bfloat162* row2 = (const __nv_bfloat162*)(g_xbz + (size_t)bt * 2048 + d);
    __nv_bfloat162 zero2; zero2.x = __float2bfloat16(0.f); zero2.y = __float2bfloat16(0.f);
    __nv_bfloat162 c2 = *row2;
    __nv_bfloat162 c1 = (t >= 1) ? *(const __nv_bfloat162*)(g_xbz + (size_t)(bt-1) * 2048 + d) : zero2;
    __nv_bfloat162 c0 = (t >= 2) ? *(const __nv_bfloat162*)(g_xbz + (size_t)(bt-2) * 2048 + d) : zero2;
    float w00 = conv_w[d*3+0], w01 = conv_w[d*3+1], w02 = conv_w[d*3+2];
    float w10 = conv_w[d*3+3], w11 = conv_w[d*3+4], w12 = conv_w[d*3+5];
    float r0 = __bfloat162float(c0.x)*w00 + __bfloat162float(c1.x)*w01 + __bfloat162float(c2.x)*w02 + conv_b[d];
    float r1 = __bfloat162float(c0.y)*w10 + __bfloat162float(c1.y)*w11 + __bfloat162float(c2.y)*w12 + conv_b[d+1];
    r0 = siluf(r0); r1 = siluf(r1);
    *(__nv_bfloat162*)(g_xc + (size_t)bt * 1024 + d) = __floats2bfloat162_rn(r0, r1);
}

// ---------------- scan prep ----------------
__global__ void prep_scan_kernel(const float* __restrict__ Aparam, const float* __restrict__ Bb,
                                 const float* __restrict__ db){
    __shared__ float sm[64][129];
    int row0 = blockIdx.x * 64;
    int tid = threadIdx.x;
    for (int idx = tid; idx < 64*128; idx += 256){
        int r = idx >> 7, c = idx & 127;
        sm[r][c] = g_proj[(size_t)(row0 + r) * 1152 + c];
    }
    __syncthreads();
    int b = row0 >> 12;
    int t0 = row0 & (T_ - 1);
    for (int idx = tid; idx < 64*64; idx += 256){
        int h = idx >> 6, tt = idx & 63;
        float p1 = sm[tt][h], p2 = sm[tt][64 + h];
        float delta = softplusf(p1 + db[h]);
        float alog = -softplusf(Aparam[h]);
        size_t o = (size_t)(b * 64 + h) * 4096 + t0 + tt;
        g_a[o]  = delta * alog;
        g_bu[o] = delta * (p2 + Bb[h]);
    }
}

// ---------------- block-parallel scan over T per (b,h) ----------------
__device__ __forceinline__ float block_excl_prefix(float total, float* wsum, int tid){
    __syncthreads();
    int lane = tid & 31, wid = tid >> 5;
    float v = total;
    #pragma unroll
    for (int d = 1; d < 32; d <<= 1){
        float o = __shfl_up_sync(0xffffffffu, v, d);
        if (lane >= d) v += o;
    }
    if (lane == 31) wsum[wid] = v;
    __syncthreads();
    if (tid == 0){
        float s = 0.f;
        for (int i = 0; i < 16; i++){ float t = wsum[i]; wsum[i] = s; s += t; }
    }
    __syncthreads();
    return wsum[wid] + v - total;
}

__global__ void scan_kernel(){
    __shared__ float wsum[16];
    int bh = blockIdx.x;
    int b = bh >> 6, hh = bh & 63;
    int tid = threadIdx.x;
    size_t base = (size_t)bh * 4096 + tid * 8;
    float av[8], bv[8], ev[8], cv[8];
    {
        float4 a0 = *(const float4*)(g_a + base);
        float4 a1 = *(const float4*)(g_a + base + 4);
        av[0]=a0.x; av[1]=a0.y; av[2]=a0.z; av[3]=a0.w;
        av[4]=a1.x; av[5]=a1.y; av[6]=a1.z; av[7]=a1.w;
        float4 b0 = *(const float4*)(g_bu + base);
        float4 b1 = *(const float4*)(g_bu + base + 4);
        bv[0]=b0.x; bv[1]=b0.y; bv[2]=b0.z; bv[3]=b0.w;
        bv[4]=b1.x; bv[5]=b1.y; bv[6]=b1.z; bv[7]=b1.w;
    }
    float s = 0.f;
    #pragma unroll
    for (int i = 0; i < 8; i++){ s += av[i]; av[i] = s; }
    float pa = block_excl_prefix(av[7], wsum, tid);
    #pragma unroll
    for (int i = 0; i < 8; i++){
        float S = pa + av[i];
        float Sprev = pa + (i ? av[i-1] : 0.f);
        ev[i] = expf(clipf(S));
        cv[i] = bv[i] * expf(-clipf(Sprev));
    }
    s = 0.f;
    #pragma unroll
    for (int i = 0; i < 8; i++){ s += cv[i]; cv[i] = s; }
    float pb = block_excl_prefix(cv[7], wsum, tid);
    int t = tid * 8;
    #pragma unroll
    for (int i = 0; i < 8; i++){
        float hval = ev[i] * (pb + cv[i]);
        g_h[(size_t)(b * T_ + t + i) * 64 + hh] = __float2bfloat16(hval);
    }
}

// ---------------- tcgen05 GEMM: C[M,N] = A[M,K] @ W[N,K]^T, fused epilogues ----------------
// EPI 0: store bf16 to g_xbz (ld 2048)
// EPI 1: store f32  to g_proj (ld 1152)
// EPI 2: u = (acc + Cb + Db + projDw) * silu(z) -> g_u bf16
// EPI 3: out = acc + x (fp32)
// 256 threads; superchunk = 128 K (2 stages of 64); ring of 4 stages (2 SCs).
template<int EPI, int KDIM, int NTILE>
__global__ void __launch_bounds__(256, 1) gemm_tc(
    const float* __restrict__ aux0, const float* __restrict__ aux1,
    const float* __restrict__ xres, float* __restrict__ outp)
{
    const __nv_bfloat16* __restrict__ Ag = (EPI==0) ? g_xn : (EPI==1) ? g_xc : (EPI==2) ? g_h : g_u;
    const __nv_bfloat16* __restrict__ Wg = (EPI==0) ? g_Wa : (EPI==1) ? g_Wb : (EPI==2) ? g_Wc : g_Wd;
    extern __shared__ __align__(1024) char smem_raw[];
    constexpr int SPS = (KDIM >= 128) ? 2 : 1;       // stages per superchunk
    constexpr int NSC = KDIM / (64 * SPS);           // number of superchunks
    constexpr int STAGE = 16384 + NTILE * 128;       // A tile 16KB + W tile
    constexpr uint32_t IDESC = (1u<<4) | (1u<<7) | (1u<<10) | ((NTILE/8u)<<17) | (8u<<24);

    const int tid = threadIdx.x, lane = tid & 31, warp = tid >> 5;
    const size_t m0 = (size_t)blockIdx.y * 128;
    const int n0 = blockIdx.x * NTILE;
    const uint32_t sbase = (uint32_t)__cvta_generic_to_shared(smem_raw);
    const uint32_t mb = sbase + 16;                  // 2 mbarriers

    if (warp == 0) tc_alloc(sbase, 256u);
    if (tid == 0){
        asm volatile("mbarrier.init.shared.b64 [%0], 1;" :: "r"(mb) : "memory");
        asm volatile("mbarrier.init.shared.b64 [%0], 1;" :: "r"(mb + 8) : "memory");
    }
    __syncthreads();
    uint32_t tmem;
    asm volatile("ld.shared.b32 %0, [%1];" : "=r"(tmem) : "r"(sbase));

    auto load_stage = [&](int kk, int st){
        uint32_t abase = sbase + 1024 + st * STAGE;
        uint32_t wbase = abase + 16384;
        const __nv_bfloat16* As = Ag + m0 * KDIM + kk * 64;
        const __nv_bfloat16* Ws = Wg + (size_t)n0 * KDIM + kk * 64;
        #pragma unroll
        for (int i = 0; i < 4; i++){
            int idx = i * 256 + tid;
            int r = idx >> 3, c = idx & 7;
            cpa16(abase + r*128 + ((c ^ (r & 7)) << 4), As + (size_t)r * KDIM + c * 8);
        }
        #pragma unroll
        for (int i = 0; i < NTILE/32; i++){
            int idx = i * 256 + tid;
            int r = idx >> 3, c = idx & 7;
            cpa16(wbase + r*128 + ((c ^ (r & 7)) << 4), Ws + (size_t)r * KDIM + c * 8);
        }
    };
    auto load_sc = [&](int j){
        #pragma unroll
        for (int s = 0; s < SPS; s++)
            load_stage(j*SPS + s, (j*SPS + s) & 3);
        cpa_commit();
    };

    load_sc(0);
    for (int j = 0; j < NSC; j++){
        cpa_wait0();                  // superchunk j resident
        __syncthreads();
        if (tid == 0){
            asm volatile("fence.proxy.async.shared::cta;" ::: "memory");
            #pragma unroll
            for (int s = 0; s < SPS; s++){
                uint32_t ab = sbase + 1024 + (uint32_t)(((j*SPS + s) & 3)) * STAGE;
                uint64_t ad = sdesc(ab), bd = sdesc(ab + 16384);
                #pragma unroll
                for (int ks = 0; ks < 4; ks++)
                    mma_f16_ss(tmem, ad + ks*2, bd + ks*2, IDESC,
                               (j == 0 && s == 0 && ks == 0) ? 0u : 1u);
            }
            tc_commit(mb + 8*(j & 1));
        }
        if (j + 1 < NSC){
            if (j >= 1) mbar_wait(mb + 8*((j-1) & 1), ((j-1) >> 1) & 1);
            load_sc(j + 1);
        }
    }
    mbar_wait(mb + 8*((NSC-1) & 1), ((NSC-1) >> 1) & 1);
    tc_fence_after();
    __syncthreads();

    // ---- direct TMEM -> global epilogue: 8 warps, no smem transpose ----
    // warp w: TMEM lanes (w&3)*32 (rows), col half (w>>2)*(NTILE/2)
    {
        const int rowgrp = warp & 3;
        const int half   = warp >> 2;
        const int m      = (int)m0 + rowgrp * 32 + lane;
        const uint32_t woff = (uint32_t)rowgrp << 21;
        constexpr int GPW = NTILE / 64;              // 32-col groups per warp
        #pragma unroll
        for (int g = 0; g < GPW; g++){
            const int col = half * (NTILE/2) + g * 32;
            const int nb = n0 + col;
            uint32_t r32[32];
            ldtm32(tmem + woff + col, r32);
            tc_wait_ld();
            #pragma unroll
            for (int q = 0; q < 4; q++){             // 8 cols per chunk
                float v[8];
                #pragma unroll
                for (int i = 0; i < 8; i++) v[i] = __uint_as_float(r32[q*8 + i]);
                int nbq = nb + q*8;
                if (EPI == 0){
                    uint32_t p[4];
                    #pragma unroll
                    for (int i = 0; i < 4; i++){
                        __nv_bfloat162 t2 = __floats2bfloat162_rn(v[2*i], v[2*i+1]);
                        p[i] = *(uint32_t*)&t2;
                    }
                    *(uint4*)(g_xbz + (size_t)m * 2048 + nbq) = make_uint4(p[0],p[1],p[2],p[3]);
                } else if (EPI == 1){
                    *(float4*)(g_proj + (size_t)m * 1152 + nbq) = make_float4(v[0],v[1],v[2],v[3]);
                    *(float4*)(g_proj + (size_t)m * 1152 + nbq + 4) = make_float4(v[4],v[5],v[6],v[7]);
                } else if (EPI == 2){
                    uint4 zz = *(const uint4*)(g_xbz + (size_t)m * 2048 + 1024 + nbq);
                    float4 d0 = *(const float4*)(g_proj + (size_t)m * 1152 + 128 + nbq);
                    float4 d1 = *(const float4*)(g_proj + (size_t)m * 1152 + 128 + nbq + 4);
                    const uint32_t* zp = &zz.x;
                    const float* dp0 = &d0.x; const float* dp1 = &d1.x;
                    uint32_t p[4];
                    #pragma unroll
                    for (int i = 0; i < 4; i++){
                        __nv_bfloat162 z2 = *(__nv_bfloat162*)&zp[i];
                        float dA = (i < 2) ? dp0[2*i]   : dp1[2*i-4];
                        float dB = (i < 2) ? dp0[2*i+1] : dp1[2*i-3];
                        float u0 = (v[2*i]   + aux0[nbq+2*i]   + aux1[nbq+2*i]   + dA) * siluf(__bfloat162float(z2.x));
                        float u1 = (v[2*i+1] + aux0[nbq+2*i+1] + aux1[nbq+2*i+1] + dB) * siluf(__bfloat162float(z2.y));
                        __nv_bfloat162 t2 = __floats2bfloat162_rn(u0, u1);
                        p[i] = *(uint32_t*)&t2;
                    }
                    *(uint4*)(g_u + (size_t)m * 1024 + nbq) = make_uint4(p[0],p[1],p[2],p[3]);
                } else {
                    float4 x0 = *(const float4*)(xres + (size_t)m * 1024 + nbq);
                    float4 x1 = *(const float4*)(xres + (size_t)m * 1024 + nbq + 4);
                    *(float4*)(outp + (size_t)m * 1024 + nbq) =
                        make_float4(v[0]+x0.x, v[1]+x0.y, v[2]+x0.z, v[3]+x0.w);
                    *(float4*)(outp + (size_t)m * 1024 + nbq + 4) =
                        make_float4(v[4]+x1.x, v[5]+x1.y, v[6]+x1.z, v[7]+x1.w);
                }
            }
        }
    }
    __syncthreads();
    if (warp == 0) tc_dealloc(tmem, 256u);
}

// ---------------- launch ----------------
extern "C" void kernel_launch(void* const* d_in, const int* in_sizes, int n_in,
                              void* d_out, int out_size){
    const float* x      = (const float*)d_in[0];
    const float* norm_w = (const float*)d_in[1];
    const float* W1     = (const float*)d_in[2];
    const float* W2     = (const float*)d_in[3];
    const float* Wlast  = (const float*)d_in[4];
    const float* conv_w = (const float*)d_in[5];
    const float* conv_b = (const float*)d_in[6];
    const float* Ap     = (const float*)d_in[7];
    const float* Bw     = (const float*)d_in[8];
    const float* Bb     = (const float*)d_in[9];
    const float* Cw     = (const float*)d_in[10];
    const float* Cb     = (const float*)d_in[11];
    const float* Dw     = (const float*)d_in[12];
    const float* Db     = (const float*)d_in[13];
    const float* dwp    = (const float*)d_in[14];
    const float* dbp    = (const float*)d_in[15];
    float* out = (float*)d_out;

    const int SM256 = 1024 + 4*(16384 + 256*128);   // 197632
    const int SM128 = 1024 + 4*(16384 + 128*128);   // 132096
    cudaFuncSetAttribute((const void*)gemm_tc<0,1024,256>, cudaFuncAttributeMaxDynamicSharedMemorySize, SM256);
    cudaFuncSetAttribute((const void*)gemm_tc<1,1024,128>, cudaFuncAttributeMaxDynamicSharedMemorySize, SM128);
    cudaFuncSetAttribute((const void*)gemm_tc<2,64,256>,   cudaFuncAttributeMaxDynamicSharedMemorySize, SM256);
    cudaFuncSetAttribute((const void*)gemm_tc<3,1024,256>, cudaFuncAttributeMaxDynamicSharedMemorySize, SM256);

    convert_weights<<<17152, 256>>>(W1, W2, dwp, Bw, Dw, Cw, Wlast);
    rmsnorm_kernel<<<32768, 256>>>(x, norm_w);
    gemm_tc<0,1024,256><<<dim3(8, 256), 256, SM256>>>(nullptr, nullptr, nullptr, nullptr);
    conv_silu_kernel<<<65536, 256>>>(conv_w, conv_b);
    gemm_tc<1,1024,128><<<dim3(9, 256), 256, SM128>>>(nullptr, nullptr, nullptr, nullptr);
    prep_scan_kernel<<<512, 256>>>(Ap, Bb, dbp);
    scan_kernel<<<512, 512>>>();
    gemm_tc<2,64,256><<<dim3(4, 256), 256, SM256>>>(Cb, Db, nullptr, nullptr);
    gemm_tc<3,1024,256><<<dim3(4, 256), 256, SM256>>>(nullptr, nullptr, x, out);
}

// round 5
// speedup vs baseline: 1.6266x; 1.1597x over previous
#include <cuda_runtime.h>
#include <cuda_bf16.h>
#include <cstdint>
#include <math.h>

#define B_ 8
#define T_ 4096
#define D_ 1024
#define H_ 64
#define BT_ (B_*T_)   // 32768

#if defined(__CUDA_ARCH_FEAT_SM103_ALL) || defined(__CUDA_ARCH_FEAT_SM100_ALL)
#define HAS_TC 1
#else
#define HAS_TC 0
#endif

// ---------------- scratch ----------------
__device__ __nv_bfloat16 g_xn [(size_t)BT_*D_];
__device__ __nv_bfloat16 g_xbz[(size_t)BT_*2048];
__device__ __nv_bfloat16 g_xc [(size_t)BT_*D_];
__device__ float         g_proj[(size_t)BT_*1152];
__device__ float         g_a  [(size_t)512*4096];
__device__ float         g_bu [(size_t)512*4096];
__device__ __nv_bfloat16 g_h  [(size_t)BT_*H_];
__device__ __nv_bfloat16 g_u  [(size_t)BT_*D_];
__device__ __nv_bfloat16 g_Wa [(size_t)2048*1024];
__device__ __nv_bfloat16 g_Wb [(size_t)1152*1024];
__device__ __nv_bfloat16 g_Wc [(size_t)1024*64];
__device__ __nv_bfloat16 g_Wd [(size_t)1024*1024];

// ---------------- helpers ----------------
__device__ __forceinline__ float siluf(float v){ return v / (1.f + expf(-v)); }
__device__ __forceinline__ float softplusf(float v){ return (v > 20.f) ? v : log1pf(expf(v)); }
__device__ __forceinline__ float clipf(float v){ return fminf(fmaxf(v, -20.f), 20.f); }

__device__ __forceinline__ void cpa16(uint32_t d, const void* s){
    asm volatile("cp.async.cg.shared.global [%0], [%1], 16;\n" :: "r"(d), "l"(s));
}
__device__ __forceinline__ void cpa_commit(){
    asm volatile("cp.async.commit_group;\n" ::: "memory");
}
__device__ __forceinline__ void cpa_wait_n(int n){
    if (n <= 0)      asm volatile("cp.async.wait_group 0;\n" ::: "memory");
    else             asm volatile("cp.async.wait_group 1;\n" ::: "memory");
}
__device__ __forceinline__ void mbar_wait(uint32_t addr, uint32_t parity){
    asm volatile(
        "{\n\t.reg .pred P;\n"
        "W_%=:\n\t"
        "mbarrier.try_wait.parity.shared.b64 P, [%0], %1;\n\t"
        "@P bra D_%=;\n\t"
        "bra W_%=;\n"
        "D_%=:\n\t}"
        :: "r"(addr), "r"(parity) : "memory");
}
__device__ __forceinline__ uint64_t sdesc(uint32_t a){
    return ((uint64_t)2 << 61) | ((uint64_t)1 << 46) | ((uint64_t)64 << 32)
         | ((uint64_t)1 << 16) | ((a >> 4) & 0x3FFF);
}
__device__ __forceinline__ void mma_f16_ss(uint32_t dt, uint64_t ad, uint64_t bd,
                                           uint32_t idesc, uint32_t en){
#if HAS_TC
    asm volatile(
        "{\n\t.reg .pred p;\n\t"
        "setp.ne.u32 p, %5, 0;\n\t"
        "tcgen05.mma.cta_group::1.kind::f16 [%0], %1, %2, %3, {%4,%4,%4,%4}, p;\n\t}"
        :: "r"(dt), "l"(ad), "l"(bd), "r"(idesc), "r"(0u), "r"(en) : "memory");
#endif
}
__device__ __forceinline__ void ldtm32(uint32_t addr, uint32_t* r){
#if HAS_TC
    asm volatile(
        "tcgen05.ld.sync.aligned.32x32b.x32.b32 "
        "{%0,%1,%2,%3,%4,%5,%6,%7,%8,%9,%10,%11,%12,%13,%14,%15,"
        "%16,%17,%18,%19,%20,%21,%22,%23,%24,%25,%26,%27,%28,%29,%30,%31}, [%32];"
        : "=r"(r[0]),"=r"(r[1]),"=r"(r[2]),"=r"(r[3]),"=r"(r[4]),"=r"(r[5]),"=r"(r[6]),"=r"(r[7]),
          "=r"(r[8]),"=r"(r[9]),"=r"(r[10]),"=r"(r[11]),"=r"(r[12]),"=r"(r[13]),"=r"(r[14]),"=r"(r[15]),
          "=r"(r[16]),"=r"(r[17]),"=r"(r[18]),"=r"(r[19]),"=r"(r[20]),"=r"(r[21]),"=r"(r[22]),"=r"(r[23]),
          "=r"(r[24]),"=r"(r[25]),"=r"(r[26]),"=r"(r[27]),"=r"(r[28]),"=r"(r[29]),"=r"(r[30]),"=r"(r[31])
        : "r"(addr));
#else
    #pragma unroll
    for (int i = 0; i < 32; i++) r[i] = 0u;
    (void)addr;
#endif
}
__device__ __forceinline__ void tc_alloc(uint32_t smem_addr, uint32_t ncols){
#if HAS_TC
    asm volatile("tcgen05.alloc.cta_group::1.sync.aligned.shared::cta.b32 [%0], %1;"
                 :: "r"(smem_addr), "r"(ncols) : "memory");
#endif
}
__device__ __forceinline__ void tc_dealloc(uint32_t tmem, uint32_t ncols){
#if HAS_TC
    asm volatile("tcgen05.relinquish_alloc_permit.cta_group::1.sync.aligned;");
    asm volatile("tcgen05.dealloc.cta_group::1.sync.aligned.b32 %0, %1;" :: "r"(tmem), "r"(ncols));
#endif
}
__device__ __forceinline__ void tc_commit(uint32_t mbar){
#if HAS_TC
    asm volatile("tcgen05.commit.cta_group::1.mbarrier::arrive::one.shared::cluster.b64 [%0];"
                 :: "r"(mbar) : "memory");
#endif
}
__device__ __forceinline__ void tc_fence_after(){
#if HAS_TC
    asm volatile("tcgen05.fence::after_thread_sync;" ::: "memory");
#endif
}
__device__ __forceinline__ void tc_wait_ld(){
#if HAS_TC
    asm volatile("tcgen05.wait::ld.sync.aligned;" ::: "memory");
#endif
}

// ---------------- weight conversion ----------------
__global__ void convert_weights(const float* __restrict__ W1, const float* __restrict__ W2,
                                const float* __restrict__ dwp, const float* __restrict__ Bwp,
                                const float* __restrict__ Dwp, const float* __restrict__ Cwp,
                                const float* __restrict__ Wlastp){
    int i = blockIdx.x * blockDim.x + threadIdx.x;
    const int NWa = 2048*1024, NWb = 1152*1024, NWc = 1024*64, NWd = 1024*1024;
    if (i < NWa){
        g_Wa[i] = __float2bfloat16(i < 1048576 ? W1[i] : W2[i - 1048576]);
    } else if (i < NWa + NWb){
        int j = i - NWa;
        float v = (j < 65536) ? dwp[j] : (j < 131072) ? Bwp[j - 65536] : Dwp[j - 131072];
        g_Wb[j] = __float2bfloat16(v);
    } else if (i < NWa + NWb + NWc){
        int j = i - NWa - NWb;
        g_Wc[j] = __float2bfloat16(Cwp[j]);
    } else if (i < NWa + NWb + NWc + NWd){
        int j = i - NWa - NWb - NWc;
        g_Wd[j] = __float2bfloat16(Wlastp[j]);
    }
}

// ---------------- RMSNorm ----------------
__global__ void rmsnorm_kernel(const float* __restrict__ x, const float* __restrict__ w){
    __shared__ float ws[8];
    int m = blockIdx.x, tid = threadIdx.x;
    float4 v = ((const float4*)(x + (size_t)m * D_))[tid];
    float ss = v.x*v.x + v.y*v.y + v.z*v.z + v.w*v.w;
    #pragma unroll
    for (int d = 16; d; d >>= 1) ss += __shfl_xor_sync(0xffffffffu, ss, d);
    if ((tid & 31) == 0) ws[tid >> 5] = ss;
    __syncthreads();
    if (tid == 0){ float s = 0.f; for (int i = 0; i < 8; i++) s += ws[i]; ws[0] = s; }
    __syncthreads();
    float scale = rsqrtf(ws[0] * (1.f / D_) + 1.1920928955078125e-07f);
    float4 wv = ((const float4*)w)[tid];
    __nv_bfloat162 p0 = __floats2bfloat162_rn(v.x*scale*wv.x, v.y*scale*wv.y);
    __nv_bfloat162 p1 = __floats2bfloat162_rn(v.z*scale*wv.z, v.w*scale*wv.w);
    __nv_bfloat162* dst = (__nv_bfloat162*)(g_xn + (size_t)m * D_) + tid * 2;
    dst[0] = p0; dst[1] = p1;
}

// ---------------- causal depthwise conv (k=3) + SiLU; 4 t per thread ----------------
__global__ void conv_silu_kernel(const float* __restrict__ conv_w, const float* __restrict__ conv_b){
    int idx = blockIdx.x * blockDim.x + threadIdx.x;   // 8*1024*512 threads
    int d2 = idx & 511;
    int rest = idx >> 9;
    int tq = (rest & 1023) * 4;
    int b = rest >> 10;
    int d = d2 * 2;
    __nv_bfloat162 zero2; zero2.x = __float2bfloat16(0.f); zero2.y = __float2bfloat16(0.f);
    __nv_bfloat162 v[6];
    #pragma unroll
    for (int i = 0; i < 6; i++){
        int t = tq - 2 + i;
        v[i] = (t >= 0) ? *(const __nv_bfloat162*)(g_xbz + ((size_t)b*T_ + t)*2048 + d) : zero2;
    }
    float w00 = conv_w[d*3+0], w01 = conv_w[d*3+1], w02 = conv_w[d*3+2];
    float w10 = conv_w[d*3+3], w11 = conv_w[d*3+4], w12 = conv_w[d*3+5];
    float b0 = conv_b[d], b1 = conv_b[d+1];
    #pragma unroll
    for (int k = 0; k < 4; k++){
        float r0 = __bfloat162float(v[k].x)*w00 + __bfloat162float(v[k+1].x)*w01
                 + __bfloat162float(v[k+2].x)*w02 + b0;
        float r1 = __bfloat162float(v[k].y)*w10 + __bfloat162float(v[k+1].y)*w11
                 + __bfloat162float(v[k+2].y)*w12 + b1;
        *(__nv_bfloat162*)(g_xc + ((size_t)b*T_ + tq + k)*1024 + d) =
            __floats2bfloat162_rn(siluf(r0), siluf(r1));
    }
}

// ---------------- scan prep ----------------
__global__ void prep_scan_kernel(const float* __restrict__ Aparam, const float* __restrict__ Bb,
                                 const float* __restrict__ db){
    __shared__ float sm[64][129];
    int row0 = blockIdx.x * 64;
    int tid = threadIdx.x;
    for (int idx = tid; idx < 64*128; idx += 256){
        int r = idx >> 7, c = idx & 127;
        sm[r][c] = g_proj[(size_t)(row0 + r) * 1152 + c];
    }
    __syncthreads();
    int b = row0 >> 12;
    int t0 = row0 & (T_ - 1);
    for (int idx = tid; idx < 64*64; idx += 256){
        int h = idx >> 6, tt = idx & 63;
        float p1 = sm[tt][h], p2 = sm[tt][64 + h];
        float delta = softplusf(p1 + db[h]);
        float alog = -softplusf(Aparam[h]);
        size_t o = (size_t)(b * 64 + h) * 4096 + t0 + tt;
        g_a[o]  = delta * alog;
        g_bu[o] = delta * (p2 + Bb[h]);
    }
}

// ---------------- block-parallel scan ----------------
__device__ __forceinline__ float block_excl_prefix(float total, float* wsum, int tid){
    __syncthreads();
    int lane = tid & 31, wid = tid >> 5;
    float v = total;
    #pragma unroll
    for (int d = 1; d < 32; d <<= 1){
        float o = __shfl_up_sync(0xffffffffu, v, d);
        if (lane >= d) v += o;
    }
    if (lane == 31) wsum[wid] = v;
    __syncthreads();
    if (tid == 0){
        float s = 0.f;
        for (int i = 0; i < 16; i++){ float t = wsum[i]; wsum[i] = s; s += t; }
    }
    __syncthreads();
    return wsum[wid] + v - total;
}

__global__ void scan_kernel(){
    __shared__ float wsum[16];
    int bh = blockIdx.x;
    int b = bh >> 6, hh = bh & 63;
    int tid = threadIdx.x;
    size_t base = (size_t)bh * 4096 + tid * 8;
    float av[8], bv[8], ev[8], cv[8];
    {
        float4 a0 = *(const float4*)(g_a + base);
        float4 a1 = *(const float4*)(g_a + base + 4);
        av[0]=a0.x; av[1]=a0.y; av[2]=a0.z; av[3]=a0.w;
        av[4]=a1.x; av[5]=a1.y; av[6]=a1.z; av[7]=a1.w;
        float4 b0 = *(const float4*)(g_bu + base);
        float4 b1 = *(const float4*)(g_bu + base + 4);
        bv[0]=b0.x; bv[1]=b0.y; bv[2]=b0.z; bv[3]=b0.w;
        bv[4]=b1.x; bv[5]=b1.y; bv[6]=b1.z; bv[7]=b1.w;
    }
    float s = 0.f;
    #pragma unroll
    for (int i = 0; i < 8; i++){ s += av[i]; av[i] = s; }
    float pa = block_excl_prefix(av[7], wsum, tid);
    #pragma unroll
    for (int i = 0; i < 8; i++){
        float S = pa + av[i];
        float Sprev = pa + (i ? av[i-1] : 0.f);
        ev[i] = expf(clipf(S));
        cv[i] = bv[i] * expf(-clipf(Sprev));
    }
    s = 0.f;
    #pragma unroll
    for (int i = 0; i < 8; i++){ s += cv[i]; cv[i] = s; }
    float pb = block_excl_prefix(cv[7], wsum, tid);
    int t = tid * 8;
    #pragma unroll
    for (int i = 0; i < 8; i++){
        float hval = ev[i] * (pb + cv[i]);
        g_h[(size_t)(b * T_ + t + i) * 64 + hh] = __float2bfloat16(hval);
    }
}

// ---------------- tcgen05 GEMM: M-tile 256 (two 128-row halves in TMEM), N-tile NTILE ----------------
// EPI 0: bf16 -> g_xbz (ld 2048); EPI 1: f32 -> g_proj (ld 1152)
// EPI 2: u = (acc + Cb + Db + projDw) * silu(z) -> g_u; EPI 3: out = acc + x
template<int EPI, int KDIM, int NTILE>
__global__ void __launch_bounds__(256, 1) gemm_tc(
    const float* __restrict__ aux0, const float* __restrict__ aux1,
    const float* __restrict__ xres, float* __restrict__ outp)
{
    const __nv_bfloat16* __restrict__ Ag = (EPI==0) ? g_xn : (EPI==1) ? g_xc : (EPI==2) ? g_h : g_u;
    const __nv_bfloat16* __restrict__ Wg = (EPI==0) ? g_Wa : (EPI==1) ? g_Wb : (EPI==2) ? g_Wc : g_Wd;
    extern __shared__ __align__(1024) char smem_raw[];
    constexpr int NSC = KDIM / 64;                    // K stages of 64
    constexpr int STAGE = 32768 + NTILE * 128;        // A(256x64) 32KB + W(NTILEx64)
    constexpr uint32_t IDESC = (1u<<4) | (1u<<7) | (1u<<10) | ((NTILE/8u)<<17) | (8u<<24);

    const int tid = threadIdx.x, lane = tid & 31, warp = tid >> 5;
    const size_t m0 = (size_t)blockIdx.y * 256;
    const int n0 = blockIdx.x * NTILE;
    const uint32_t sbase = (uint32_t)__cvta_generic_to_shared(smem_raw);
    const uint32_t mb = sbase + 16;                   // 3 mbarriers

    if (warp == 0) tc_alloc(sbase, 512u);
    if (tid == 0){
        #pragma unroll
        for (int s = 0; s < 3; s++)
            asm volatile("mbarrier.init.shared.b64 [%0], 1;" :: "r"(mb + 8*s) : "memory");
    }
    __syncthreads();
    uint32_t tmem;
    asm volatile("ld.shared.b32 %0, [%1];" : "=r"(tmem) : "r"(sbase));

    auto load_sc = [&](int j){
        int st = j % 3;
        uint32_t abase = sbase + 1024 + st * STAGE;
        uint32_t wbase = abase + 32768;
        const __nv_bfloat16* As = Ag + m0 * KDIM + j * 64;
        const __nv_bfloat16* Ws = Wg + (size_t)n0 * KDIM + j * 64;
        #pragma unroll
        for (int i = 0; i < 8; i++){                  // 256 rows x 8 chunks
            int idx = i * 256 + tid;
            int r = idx >> 3, c = idx & 7;
            int rr = r & 127;
            cpa16(abase + (r >> 7)*16384 + rr*128 + ((c ^ (rr & 7)) << 4),
                  As + (size_t)r * KDIM + c * 8);
        }
        #pragma unroll
        for (int i = 0; i < NTILE/32; i++){
            int idx = i * 256 + tid;
            int r = idx >> 3, c = idx & 7;
            cpa16(wbase + r*128 + ((c ^ (r & 7)) << 4), Ws + (size_t)r * KDIM + c * 8);
        }
        cpa_commit();
    };

    load_sc(0);
    if (NSC > 1) load_sc(1);
    for (int j = 0; j < NSC; j++){
        cpa_wait_n((NSC - 1 - j) >= 1 ? 1 : 0);       // stage j resident
        __syncthreads();
        if (tid == 0){
            asm volatile("fence.proxy.async.shared::cta;" ::: "memory");
            uint32_t ab = sbase + 1024 + (uint32_t)(j % 3) * STAGE;
            uint64_t a0d = sdesc(ab), a1d = sdesc(ab + 16384), bd = sdesc(ab + 32768);
            #pragma unroll
            for (int ks = 0; ks < 4; ks++)
                mma_f16_ss(tmem, a0d + ks*2, bd + ks*2, IDESC, (j == 0 && ks == 0) ? 0u : 1u);
            #pragma unroll
            for (int ks = 0; ks < 4; ks++)
                mma_f16_ss(tmem + NTILE, a1d + ks*2, bd + ks*2, IDESC, (j == 0 && ks == 0) ? 0u : 1u);
            tc_commit(mb + 8*(j % 3));
        }
        if (j + 2 < NSC){
            if (j >= 1) mbar_wait(mb + 8*((j-1) % 3), (((j-1) / 3) & 1));
            load_sc(j + 2);
        }
    }
    mbar_wait(mb + 8*((NSC-1) % 3), (((NSC-1) / 3) & 1));
    tc_fence_after();
    __syncthreads();

    // ---- direct TMEM -> global epilogue: warps 0-3 rows 0-127 (cols [0,NTILE)),
    //      warps 4-7 rows 128-255 (cols [NTILE,2*NTILE)) ----
    {
        const int mhalf  = warp >> 2;
        const int rowgrp = warp & 3;
        const int m      = (int)m0 + mhalf * 128 + rowgrp * 32 + lane;
        const uint32_t woff = (uint32_t)rowgrp << 21;
        constexpr int GPW = NTILE / 32;
        #pragma unroll
        for (int g = 0; g < GPW; g++){
            const int nb = n0 + g * 32;
            uint32_t r32[32];
            ldtm32(tmem + woff + mhalf * NTILE + g * 32, r32);
            tc_wait_ld();
            #pragma unroll
            for (int q = 0; q < 4; q++){
                float v[8];
                #pragma unroll
                for (int i = 0; i < 8; i++) v[i] = __uint_as_float(r32[q*8 + i]);
                int nbq = nb + q*8;
                if (EPI == 0){
                    uint32_t p[4];
                    #pragma unroll
                    for (int i = 0; i < 4; i++){
                        __nv_bfloat162 t2 = __floats2bfloat162_rn(v[2*i], v[2*i+1]);
                        p[i] = *(uint32_t*)&t2;
                    }
                    *(uint4*)(g_xbz + (size_t)m * 2048 + nbq) = make_uint4(p[0],p[1],p[2],p[3]);
                } else if (EPI == 1){
                    *(float4*)(g_proj + (size_t)m * 1152 + nbq) = make_float4(v[0],v[1],v[2],v[3]);
                    *(float4*)(g_proj + (size_t)m * 1152 + nbq + 4) = make_float4(v[4],v[5],v[6],v[7]);
                } else if (EPI == 2){
                    uint4 zz = *(const uint4*)(g_xbz + (size_t)m * 2048 + 1024 + nbq);
                    float4 d0 = *(const float4*)(g_proj + (size_t)m * 1152 + 128 + nbq);
                    float4 d1 = *(const float4*)(g_proj + (size_t)m * 1152 + 128 + nbq + 4);
                    const uint32_t* zp = &zz.x;
                    const float* dp0 = &d0.x; const float* dp1 = &d1.x;
                    uint32_t p[4];
                    #pragma unroll
                    for (int i = 0; i < 4; i++){
                        __nv_bfloat162 z2 = *(__nv_bfloat162*)&zp[i];
                        float dA = (i < 2) ? dp0[2*i]   : dp1[2*i-4];
                        float dB = (i < 2) ? dp0[2*i+1] : dp1[2*i-3];
                        float u0 = (v[2*i]   + aux0[nbq+2*i]   + aux1[nbq+2*i]   + dA) * siluf(__bfloat162float(z2.x));
                        float u1 = (v[2*i+1] + aux0[nbq+2*i+1] + aux1[nbq+2*i+1] + dB) * siluf(__bfloat162float(z2.y));
                        __nv_bfloat162 t2 = __floats2bfloat162_rn(u0, u1);
                        p[i] = *(uint32_t*)&t2;
                    }
                    *(uint4*)(g_u + (size_t)m * 1024 + nbq) = make_uint4(p[0],p[1],p[2],p[3]);
                } else {
                    float4 x0 = *(const float4*)(xres + (size_t)m * 1024 + nbq);
                    float4 x1 = *(const float4*)(xres + (size_t)m * 1024 + nbq + 4);
                    *(float4*)(outp + (size_t)m * 1024 + nbq) =
                        make_float4(v[0]+x0.x, v[1]+x0.y, v[2]+x0.z, v[3]+x0.w);
                    *(float4*)(outp + (size_t)m * 1024 + nbq + 4) =
                        make_float4(v[4]+x1.x, v[5]+x1.y, v[6]+x1.z, v[7]+x1.w);
                }
            }
        }
    }
    __syncthreads();
    if (warp == 0) tc_dealloc(tmem, 512u);
}

// ---------------- launch ----------------
extern "C" void kernel_launch(void* const* d_in, const int* in_sizes, int n_in,
                              void* d_out, int out_size){
    const float* x      = (const float*)d_in[0];
    const float* norm_w = (const float*)d_in[1];
    const float* W1     = (const float*)d_in[2];
    const float* W2     = (const float*)d_in[3];
    const float* Wlast  = (const float*)d_in[4];
    const float* conv_w = (const float*)d_in[5];
    const float* conv_b = (const float*)d_in[6];
    const float* Ap     = (const float*)d_in[7];
    const float* Bw     = (const float*)d_in[8];
    const float* Bb     = (const float*)d_in[9];
    const float* Cw     = (const float*)d_in[10];
    const float* Cb     = (const float*)d_in[11];
    const float* Dw     = (const float*)d_in[12];
    const float* Db     = (const float*)d_in[13];
    const float* dwp    = (const float*)d_in[14];
    const float* dbp    = (const float*)d_in[15];
    float* out = (float*)d_out;

    const int SM256 = 1024 + 3*(32768 + 256*128);   // 197632
    const int SM128 = 1024 + 3*(32768 + 128*128);   // 148480
    cudaFuncSetAttribute((const void*)gemm_tc<0,1024,256>, cudaFuncAttributeMaxDynamicSharedMemorySize, SM256);
    cudaFuncSetAttribute((const void*)gemm_tc<1,1024,128>, cudaFuncAttributeMaxDynamicSharedMemorySize, SM128);
    cudaFuncSetAttribute((const void*)gemm_tc<2,64,256>,   cudaFuncAttributeMaxDynamicSharedMemorySize, SM256);
    cudaFuncSetAttribute((const void*)gemm_tc<3,1024,256>, cudaFuncAttributeMaxDynamicSharedMemorySize, SM256);

    convert_weights<<<17152, 256>>>(W1, W2, dwp, Bw, Dw, Cw, Wlast);
    rmsnorm_kernel<<<32768, 256>>>(x, norm_w);
    gemm_tc<0,1024,256><<<dim3(8, 128), 256, SM256>>>(nullptr, nullptr, nullptr, nullptr);
    conv_silu_kernel<<<16384, 256>>>(conv_w, conv_b);
    gemm_tc<1,1024,128><<<dim3(9, 128), 256, SM128>>>(nullptr, nullptr, nullptr, nullptr);
    prep_scan_kernel<<<512, 256>>>(Ap, Bb, dbp);
    scan_kernel<<<512, 512>>>();
    gemm_tc<2,64,256><<<dim3(4, 128), 256, SM256>>>(Cb, Db, nullptr, nullptr);
    gemm_tc<3,1024,256><<<dim3(4, 128), 256, SM256>>>(nullptr, nullptr, x, out);
}